// round 3
// baseline (speedup 1.0000x reference)
#include <cuda_runtime.h>
#include <math.h>

// Scratch (no device allocation allowed -> __device__ globals).
// Max rows supported: 1<<17 = 131072 (this problem: 8*8192 = 65536).
#define MAX_ROWS (1 << 17)
__device__ float2 g_stats[MAX_ROWS];  // (mu, sigma) per row
__device__ float2 g_cum[MAX_ROWS];    // (mu_cum, 1/sigma_cum) per row

// ---------------------------------------------------------------------------
// Kernel 1: per-row mean + std (ddof=1). One warp per row of D floats.
// ---------------------------------------------------------------------------
__global__ void row_stats_kernel(const float* __restrict__ x, int D, int nrows) {
    int warp = (blockIdx.x * blockDim.x + threadIdx.x) >> 5;
    int lane = threadIdx.x & 31;
    if (warp >= nrows) return;

    const float4* xr = reinterpret_cast<const float4*>(x) + (size_t)warp * (D >> 2);
    int nf4 = D >> 2;
    float s = 0.f, ss = 0.f;
    for (int i = lane; i < nf4; i += 32) {
        float4 v = xr[i];
        s  += (v.x + v.y) + (v.z + v.w);
        ss += (v.x * v.x + v.y * v.y) + (v.z * v.z + v.w * v.w);
    }
#pragma unroll
    for (int o = 16; o > 0; o >>= 1) {
        s  += __shfl_xor_sync(0xffffffffu, s, o);
        ss += __shfl_xor_sync(0xffffffffu, ss, o);
    }
    if (lane == 0) {
        float mu  = s / (float)D;
        float var = fmaxf((ss - (float)D * mu * mu) / (float)(D - 1), 0.f);
        g_stats[warp] = make_float2(mu, sqrtf(var));
    }
}

// ---------------------------------------------------------------------------
// Kernel 2: per-batch weighted prefix sum over S scalars (block scan).
// mu_cum[t]    = a*h_mu    + (1-a) * sum_{u<=t} a^u * mu[u]
// sigma_cum[t] = max(a*h_sig + (1-a) * sum_{u<=t} a^u * sigma[u], EPS)
// Stores (mu_cum, 1/sigma_cum); writes h_new for t = S-1.
// One block (1024 threads) per batch. Supports S <= 16*1024.
// ---------------------------------------------------------------------------
__global__ void scan_kernel(const float* __restrict__ h,
                            const float* __restrict__ alpha_logit,
                            float* __restrict__ out_h, int S) {
    const int b    = blockIdx.x;
    const int tid  = threadIdx.x;
    const int lane = tid & 31;
    const int wid  = tid >> 5;
    const int nthr = blockDim.x;

    const float alpha = 1.f / (1.f + expf(-alpha_logit[0]));
    const float h_mu    = h[b * 2 + 0];
    const float h_sigma = h[b * 2 + 1];
    const float one_minus = 1.f - alpha;

    const int items = (S + nthr - 1) / nthr;   // <= 16
    const int base  = tid * items;

    float am[16], as[16];
    float sm = 0.f, sg = 0.f;
    for (int j = 0; j < items; j++) {
        int t = base + j;
        float wm = 0.f, ws = 0.f;
        if (t < S) {
            float w = powf(alpha, (float)t);
            float2 st = g_stats[b * S + t];
            wm = w * st.x;
            ws = w * st.y;
        }
        sm += wm; sg += ws;
        am[j] = sm; as[j] = sg;
    }

    // inclusive warp scan of per-thread totals
    float m = sm, g2 = sg;
#pragma unroll
    for (int o = 1; o < 32; o <<= 1) {
        float pm = __shfl_up_sync(0xffffffffu, m, o);
        float pg = __shfl_up_sync(0xffffffffu, g2, o);
        if (lane >= o) { m += pm; g2 += pg; }
    }
    // exclusive version (exact, by shifting the inclusive scan)
    float em = __shfl_up_sync(0xffffffffu, m, 1);
    float eg = __shfl_up_sync(0xffffffffu, g2, 1);
    if (lane == 0) { em = 0.f; eg = 0.f; }

    __shared__ float2 wtot[32];
    if (lane == 31) wtot[wid] = make_float2(m, g2);
    __syncthreads();
    if (wid == 0) {
        int nw = nthr >> 5;
        float2 v = (lane < nw) ? wtot[lane] : make_float2(0.f, 0.f);
        float a = v.x, c = v.y;
#pragma unroll
        for (int o = 1; o < 32; o <<= 1) {
            float pa = __shfl_up_sync(0xffffffffu, a, o);
            float pc = __shfl_up_sync(0xffffffffu, c, o);
            if (lane >= o) { a += pa; c += pc; }
        }
        wtot[lane] = make_float2(a, c);
    }
    __syncthreads();

    float off_m = em + (wid > 0 ? wtot[wid - 1].x : 0.f);
    float off_s = eg + (wid > 0 ? wtot[wid - 1].y : 0.f);

    for (int j = 0; j < items; j++) {
        int t = base + j;
        if (t < S) {
            float mc = fmaf(one_minus, off_m + am[j], alpha * h_mu);
            float sc = fmaf(one_minus, off_s + as[j], alpha * h_sigma);
            sc = fmaxf(sc, 1e-12f);
            g_cum[b * S + t] = make_float2(mc, 1.f / sc);
            if (t == S - 1) {
                out_h[b * 2 + 0] = mc;
                out_h[b * 2 + 1] = sc;
            }
        }
    }
}

// ---------------------------------------------------------------------------
// Kernel 3: normalize, float4 vectorized, grid-stride with 2 items/thread.
// y = (x - mu_cum)*inv_sigma*gamma + beta
// d4shift >= 0: D4 is a power of two, row = i >> d4shift, d4 = i & (D4-1).
// d4shift < 0 : generic divide fallback.
// ---------------------------------------------------------------------------
__global__ void norm_kernel(const float* __restrict__ x,
                            const float* __restrict__ gamma,
                            const float* __restrict__ beta,
                            float* __restrict__ y,
                            unsigned D4, int d4shift, unsigned n4) {
    unsigned stride = blockDim.x * gridDim.x;
    for (unsigned i = blockIdx.x * blockDim.x + threadIdx.x; i < n4; i += stride) {
        unsigned row, d4;
        if (d4shift >= 0) {
            row = i >> d4shift;
            d4  = i & (D4 - 1u);
        } else {
            row = i / D4;
            d4  = i - row * D4;
        }
        float4 xv = reinterpret_cast<const float4*>(x)[i];
        float2 c  = g_cum[row];
        float4 gv = reinterpret_cast<const float4*>(gamma)[d4];
        float4 bv = reinterpret_cast<const float4*>(beta)[d4];

        float4 o;
        o.x = fmaf((xv.x - c.x) * c.y, gv.x, bv.x);
        o.y = fmaf((xv.y - c.x) * c.y, gv.y, bv.y);
        o.z = fmaf((xv.z - c.x) * c.y, gv.z, bv.z);
        o.w = fmaf((xv.w - c.x) * c.y, gv.w, bv.w);
        reinterpret_cast<float4*>(y)[i] = o;
    }
}

// ---------------------------------------------------------------------------
extern "C" void kernel_launch(void* const* d_in, const int* in_sizes, int n_in,
                              void* d_out, int out_size) {
    const float* x      = (const float*)d_in[0];
    const float* h      = (const float*)d_in[1];
    const float* gamma  = (const float*)d_in[2];
    const float* beta   = (const float*)d_in[3];
    const float* alogit = (const float*)d_in[4];

    const int nx = in_sizes[0];          // B*S*D
    const int B  = in_sizes[1] / 2;      // h is (B,1,2)
    const int D  = in_sizes[2];          // gamma length
    const int S  = nx / (B * D);
    const int nrows = B * S;

    float* y     = (float*)d_out;
    float* out_h = y + nx;

    // Kernel 1: one warp per row, 8 warps/block
    {
        int wpb = 8;
        int blocks = (nrows + wpb - 1) / wpb;
        row_stats_kernel<<<blocks, wpb * 32>>>(x, D, nrows);
    }
    // Kernel 2: one block per batch
    scan_kernel<<<B, 1024>>>(h, alogit, out_h, S);

    // Kernel 3: elementwise normalize (2 float4 per thread)
    {
        unsigned n4 = (unsigned)(nx >> 2);
        unsigned D4 = (unsigned)(D >> 2);
        int d4shift = -1;
        if ((D4 & (D4 - 1u)) == 0u) {            // power of two
            d4shift = 0;
            while ((1u << d4shift) < D4) d4shift++;
        }
        int tpb = 256;
        unsigned nb = (n4 / 2 + tpb - 1) / tpb;  // 2 items per thread
        if (nb == 0) nb = 1;
        norm_kernel<<<nb, tpb>>>(x, gamma, beta, y, D4, d4shift, n4);
    }
}